// round 6
// baseline (speedup 1.0000x reference)
#include <cuda_runtime.h>
#include <math.h>

// DBN beat decoder (bar-pointer Viterbi), exact replication of reference arithmetic.
// B=4, T=6000, 82 tempo blocks (tau=28..109), S=5617 states.
//
// Register-resident delta (striped s = tid + k*672, 9 slots/thread).
// Shift = __shfl_up(1); warp boundaries via 21x9 shared floats (prefetched in
// the reduction phase, barrier-separated from their writers). trans_log rows
// preloaded into registers. Backpointers compressed to 82 prev_last floats/step;
// argmax recomputed at ~90 beat jumps in backtracking (first-index tiebreak).
//
// R6 FIX: reduction shuffles were guarded by tid<656 (NOT warp-aligned) =>
// warp 20 split around full-mask __shfl_xor_sync => deadlock. Now ALL threads
// execute the shuffles; padded groups (rj>=82) read -inf pads; only the sm_fb
// store is guarded.

#define NI      82
#define MINTAU  28
#define NSTATE  5617
#define TT      6000
#define BB      4
#define NTHREADS 672
#define NWARP   21
#define NSLOTS  9      // 672*9 = 6048 >= 5617

// g_plbuf[b][t][i] = delta(t-1)[last_idx[i]]  (rows t=1..5999 used)
__device__ float g_plbuf[BB][TT + 1][NI];

__device__ __forceinline__ int base_of(int j) {
    return MINTAU * j + (j * (j - 1)) / 2;
}

__global__ void __launch_bounds__(NTHREADS, 1)
dbn_viterbi_kernel(const float* __restrict__ logit, float* __restrict__ out)
{
    extern __shared__ float sm[];
    float* sm_tl   = sm;                 // 6724
    float* sm_blp  = sm_tl + NI * NI;    // 6000
    float* sm_nblp = sm_blp + TT;        // 6000
    float* sm_pl   = sm_nblp + TT;       // 96  (pad [82..95] = -inf)
    float* sm_fb   = sm_pl + 96;         // 96
    float* sm_bnd  = sm_fb + 96;         // 192 (NWARP*NSLOTS = 189)
    float* sm_rv   = sm_bnd + 192;       // 672
    int*   sm_ri   = (int*)(sm_rv + NTHREADS); // 672

    const int tid  = threadIdx.x;
    const int lane = tid & 31;
    const int wrp  = tid >> 5;
    const int b    = blockIdx.x;
    const float* lg = logit + b * TT;
    float* outrow   = out + b * TT;

    const float NEGINF = __int_as_float(0xff800000);

    // ---- zero output row ----
    for (int t = tid; t < TT; t += NTHREADS) outrow[t] = 0.0f;

    // ---- emissions (double precision, cast to f32; validated exact in R1) ----
    for (int t = tid; t < TT; t += NTHREADS) {
        double x = (double)lg[t];
        double bl = (x >= 0.0) ? -log1p(exp(-x)) : (x - log1p(exp(x)));
        double nl = (x <= 0.0) ? -log1p(exp(x))  : (-x - log1p(exp(-x)));
        sm_blp[t]  = (float)bl;
        sm_nblp[t] = (float)nl;
    }

    // ---- trans_log rows (double precision log-softmax) ----
    if (tid < NI) {
        int i = tid;
        double ti = (double)(MINTAU + i);
        double ssum = 0.0;
        for (int j = 0; j < NI; ++j) {
            double r = -100.0 * fabs((double)(MINTAU + j) / ti - 1.0);
            ssum += exp(r);
        }
        double ls = log(ssum);  // row max is 0 (at j==i)
        for (int j = 0; j < NI; ++j) {
            double r = -100.0 * fabs((double)(MINTAU + j) / ti - 1.0);
            sm_tl[i * NI + j] = (float)(r - ls);
        }
    }
    if (tid < 14) sm_pl[82 + tid] = NEGINF;   // pad for reduction overshoot

    // ---- per-slot metadata (bounded search) ----
    int slotBlk[NSLOTS];
    unsigned firstM = 0, lastM = 0, validM = 0;
    #pragma unroll
    for (int k = 0; k < NSLOTS; ++k) {
        int s = tid + k * NTHREADS;
        bool valid = (s < NSTATE);
        int j = 0;
        if (valid) {
            while (j < NI - 1 && base_of(j + 1) <= s) ++j;
            validM |= 1u << k;
            if (s == base_of(j))         firstM |= 1u << k;
            if (s == base_of(j + 1) - 1) lastM  |= 1u << k;
        }
        slotBlk[k] = j;
    }

    const float logS = (float)log((double)NSTATE);

    __syncthreads();  // emissions + trans_log ready

    // ---- preload trans_log candidates into registers (8 lanes per j) ----
    const int rj = tid >> 3, rg = tid & 7;        // rj in [0,84); valid rj < 82
    float tlr[11];
    #pragma unroll
    for (int k2 = 0; k2 < 11; ++k2) {
        int i = rg + 8 * k2;
        tlr[k2] = (rj < NI && i < NI) ? sm_tl[i * NI + rj] : 0.0f;  // pad pl = -inf
    }

    // ---- init delta(0) in registers ----
    float v[NSLOTS];
    {
        float bt0 = sm_blp[0], nbt0 = sm_nblp[0];
        float* plrow = &g_plbuf[b][1][0];
        #pragma unroll
        for (int k = 0; k < NSLOTS; ++k) {
            if ((validM >> k) & 1u) {
                float em = ((firstM >> k) & 1u) ? bt0 : nbt0;
                float val = em - logS;
                v[k] = val;
                if ((lastM >> k) & 1u) { sm_pl[slotBlk[k]] = val; plrow[slotBlk[k]] = val; }
            } else {
                v[k] = NEGINF;
            }
        }
        if (lane == 31) {
            #pragma unroll
            for (int k = 0; k < NSLOTS; ++k) sm_bnd[wrp * NSLOTS + k] = v[k];
        }
    }

    float bval[NSLOTS];

    // ---- forward Viterbi ----
    for (int t = 1; t < TT; ++t) {
        __syncthreads();  // pl + bnd from previous update visible

        // 82x82 max-plus reduction — ALL threads run the shuffles (warp-uniform).
        // Padded groups (rj>=82) read -inf pads in sm_pl => best = -inf, discarded.
        {
            float b0 = NEGINF, b1 = NEGINF;
            #pragma unroll
            for (int k2 = 0; k2 < 10; k2 += 2) {
                b0 = fmaxf(b0, sm_pl[rg + 8 * k2]       + tlr[k2]);
                b1 = fmaxf(b1, sm_pl[rg + 8 * (k2 + 1)] + tlr[k2 + 1]);
            }
            b0 = fmaxf(b0, sm_pl[rg + 80] + tlr[10]);
            float best = fmaxf(b0, b1);
            best = fmaxf(best, __shfl_xor_sync(0xffffffffu, best, 1));
            best = fmaxf(best, __shfl_xor_sync(0xffffffffu, best, 2));
            best = fmaxf(best, __shfl_xor_sync(0xffffffffu, best, 4));
            if (rg == 0 && rj < NI) sm_fb[rj] = best;
        }
        // prefetch warp-boundary values (written in previous update phase)
        if (lane == 0) {
            #pragma unroll
            for (int k = 0; k < NSLOTS; ++k) {
                if (wrp > 0)      bval[k] = sm_bnd[(wrp - 1) * NSLOTS + k];
                else if (k > 0)   bval[k] = sm_bnd[(NWARP - 1) * NSLOTS + (k - 1)];
                else              bval[k] = NEGINF;   // state 0 is a first state
            }
        }

        __syncthreads();  // fb ready

        float bt  = sm_blp[t];
        float nbt = sm_nblp[t];
        float* plrow = &g_plbuf[b][t + 1][0];
        #pragma unroll
        for (int k = 0; k < NSLOTS; ++k) {
            float pv = __shfl_up_sync(0xffffffffu, v[k], 1);
            if (lane == 0) pv = bval[k];
            float nv = pv + nbt;
            if ((firstM >> k) & 1u) nv = sm_fb[slotBlk[k]] + bt;
            v[k] = nv;
            if ((lastM >> k) & 1u) { sm_pl[slotBlk[k]] = nv; plrow[slotBlk[k]] = nv; }
        }
        if (lane == 31) {
            #pragma unroll
            for (int k = 0; k < NSLOTS; ++k) sm_bnd[wrp * NSLOTS + k] = v[k];
        }
    }

    // ---- final argmax over delta(T-1), first-index tiebreak ----
    {
        float bv = NEGINF; int bs = NSTATE - 1;
        #pragma unroll
        for (int k = NSLOTS - 1; k >= 0; --k) {
            if ((validM >> k) & 1u) {
                int s = tid + k * NTHREADS;
                if (v[k] >= bv) { bv = v[k]; bs = s; }   // descending k => smallest s on ties
            }
        }
        sm_rv[tid] = bv; sm_ri[tid] = bs;
    }
    __syncthreads();
    if (tid < NTHREADS - 512) {  // fold 512..671 into 0..159
        float v2 = sm_rv[tid + 512]; int s2 = sm_ri[tid + 512];
        if (v2 > sm_rv[tid] || (v2 == sm_rv[tid] && s2 < sm_ri[tid])) {
            sm_rv[tid] = v2; sm_ri[tid] = s2;
        }
    }
    __syncthreads();
    for (int st = 256; st > 0; st >>= 1) {
        if (tid < st) {
            float v2 = sm_rv[tid + st]; int s2 = sm_ri[tid + st];
            if (v2 > sm_rv[tid] || (v2 == sm_rv[tid] && s2 < sm_ri[tid])) {
                sm_rv[tid] = v2; sm_ri[tid] = s2;
            }
        }
        __syncthreads();
    }

    // ---- backtrack (thread 0): jump beat-to-beat, hard-bounded ----
    if (tid == 0) {
        const double p0  = (double)0.05f;
        const double thr = log(p0 / (1.0 - p0));  // logit-space threshold

        int s = sm_ri[0];
        if (s < 0) s = 0;
        if (s >= NSTATE) s = NSTATE - 1;
        int j = 0;
        while (j < NI - 1 && base_of(j + 1) <= s) ++j;
        int p = s - base_of(j);
        int t = TT - 1;
        for (int iter = 0; iter < TT; ++iter) {   // hard bound (~220 real hops)
            if (p > t) break;          // path started mid-block: no beat
            int tb = t - p;            // beat time (position 0)
            double x = (double)lg[tb];
            outrow[tb] = (x >= thr) ? 1.0f : 0.0f;
            if (tb == 0) break;
            const float* row = &g_plbuf[b][tb][0];
            float mx = NEGINF; int bi = 0;
            for (int i = 0; i < NI; ++i) {
                float c = row[i] + sm_tl[i * NI + j];
                if (c > mx) { mx = c; bi = i; }
            }
            j = bi;
            t = tb - 1;
            p = (MINTAU + j) - 1;
        }
    }
}

extern "C" void kernel_launch(void* const* d_in, const int* in_sizes, int n_in,
                              void* d_out, int out_size)
{
    const float* logit = (const float*)d_in[0];
    float* out = (float*)d_out;

    // floats: 6724 + 6000 + 6000 + 96 + 96 + 192 + 672 + 672 = 20452
    size_t smem = 20452u * sizeof(float);
    cudaFuncSetAttribute(dbn_viterbi_kernel,
                         cudaFuncAttributeMaxDynamicSharedMemorySize, (int)smem);
    dbn_viterbi_kernel<<<BB, NTHREADS, smem>>>(logit, out);
}

// round 7
// speedup vs baseline: 2.0537x; 2.0537x over previous
#include <cuda_runtime.h>
#include <math.h>

// DBN beat decoder (bar-pointer Viterbi). B=4, T=6000, 82 blocks, S=5617.
//
// R7: issue-bandwidth redesign. Shared-memory delta (ping-pong), ONE barrier
// per step. Bulk update is branch-free: per-slot precomputed load index points
// at cur[s-1] (normal), vf[j] (position-1 slots), or a safe cell (s==0).
// First states store junk (never read; final argmax substitutes vf).
// pl_t[i] = cur[last_i-1] + nb_t computed pre-bulk (last-1 never first).
// vf_t[j] = fb_t[j] + b_t written directly by the reduction leader.
// Backpointers compressed to 82 prev_last floats/step (g_plbuf); argmax
// recomputed at ~90 beat jumps in backtracking (first-index tiebreak).

#define NI      82
#define MINTAU  28
#define NSTATE  5617
#define TT      6000
#define BB      4
#define NTHREADS 768
#define NSLOTS  8      // 768*8 = 6144 >= 5617 (pads harmless)

// shared-memory layout (float offsets)
#define OFF_B0   0          // delta buffer, even t   (6144)
#define OFF_B1   6144       // delta buffer, odd t    (6144)
#define OFF_TL   12288      // trans_log 82x82        (6724)
#define OFF_BLP  19012      // beat logprob           (6000)
#define OFF_NB   25012      // nonbeat logprob        (6000)
#define OFF_PL0  31012      // prev_last, even parity (96, pad -inf, 16B aligned)
#define OFF_PL1  31108      // prev_last, odd parity  (96)
#define OFF_VF0  31204      // virtual first, even    (96)
#define OFF_VF1  31300      // virtual first, odd     (96)
#define OFF_RV   31396      // argmax values          (768+)
#define OFF_RI   32420      // argmax indices         (768+)
#define SM_FLOATS 33444

__device__ float g_plbuf[BB][TT + 1][NI];

__device__ __forceinline__ int base_of(int j) {
    return MINTAU * j + (j * (j - 1)) / 2;
}

__global__ void __launch_bounds__(NTHREADS, 1)
dbn_viterbi_kernel(const float* __restrict__ logit, float* __restrict__ out)
{
    extern __shared__ float sm[];
    const int tid  = threadIdx.x;
    const int wrp  = tid >> 5;
    const int b    = blockIdx.x;
    const float* lg = logit + b * TT;
    float* outrow   = out + b * TT;

    const float NEGINF = __int_as_float(0xff800000);

    // ---- zero output row ----
    for (int t = tid; t < TT; t += NTHREADS) outrow[t] = 0.0f;

    // ---- emissions (double precision, cast to f32; bit-matched reference) ----
    for (int t = tid; t < TT; t += NTHREADS) {
        double x = (double)lg[t];
        double bl = (x >= 0.0) ? -log1p(exp(-x)) : (x - log1p(exp(x)));
        double nl = (x <= 0.0) ? -log1p(exp(x))  : (-x - log1p(exp(-x)));
        sm[OFF_BLP + t] = (float)bl;
        sm[OFF_NB  + t] = (float)nl;
    }

    // ---- trans_log rows (double precision log-softmax) ----
    if (tid < NI) {
        int i = tid;
        double ti = (double)(MINTAU + i);
        double ssum = 0.0;
        for (int j = 0; j < NI; ++j) {
            double r = -100.0 * fabs((double)(MINTAU + j) / ti - 1.0);
            ssum += exp(r);
        }
        double ls = log(ssum);  // row max is 0 (at j==i)
        for (int j = 0; j < NI; ++j) {
            double r = -100.0 * fabs((double)(MINTAU + j) / ti - 1.0);
            sm[OFF_TL + i * NI + j] = (float)(r - ls);
        }
    }
    if (tid < 14) {  // -inf pads for reduction overshoot, both parities
        sm[OFF_PL0 + 82 + tid] = NEGINF;
        sm[OFF_PL1 + 82 + tid] = NEGINF;
    }

    // ---- per-slot metadata: branch-free load indices + masks ----
    int lidxO[NSLOTS], lidxE[NSLOTS];
    unsigned firstM = 0, validM = 0;
    #pragma unroll
    for (int k = 0; k < NSLOTS; ++k) {
        int s = tid + k * NTHREADS;
        if (s < NSTATE) {
            validM |= 1u << k;
            int j = 0;
            while (j < NI - 1 && base_of(j + 1) <= s) ++j;
            int pos = s - base_of(j);
            if (pos == 0) firstM |= 1u << k;
            if (pos == 1)      { lidxO[k] = OFF_VF0 + j;     lidxE[k] = OFF_VF1 + j; }
            else if (s == 0)   { lidxO[k] = OFF_B0;          lidxE[k] = OFF_B1; }          // safe junk
            else               { lidxO[k] = OFF_B0 + s - 1;  lidxE[k] = OFF_B1 + s - 1; }
        } else {
            lidxO[k] = OFF_B0 + s - 1;  lidxE[k] = OFF_B1 + s - 1;   // pad, harmless
        }
    }

    // pl-extract role: tids 672..753 (warps 21-23, no shuffles there)
    const bool plThread = (tid >= 672) && (tid < 672 + NI);
    const int  plIdx    = tid - 672;
    const int  lastm1   = plThread ? (base_of(plIdx + 1) - 2) : 0;

    const float logS = (float)log((double)NSTATE);

    __syncthreads();  // emissions + trans_log ready

    // ---- preload trans_log candidates (8 lanes per j; groups padded to 84) ----
    const int rj = tid >> 3, rg = tid & 7;
    float tlr[12];
    #pragma unroll
    for (int q = 0; q < 12; ++q) {
        int i = 4 * rg + 32 * (q >> 2) + (q & 3);
        tlr[q] = (rj < NI && i < NI) ? sm[OFF_TL + i * NI + rj] : 0.0f;  // pl pad = -inf
    }

    // ---- init delta(0) into buf0 ----
    {
        float bt0 = sm[OFF_BLP + 0], nbt0 = sm[OFF_NB + 0];
        #pragma unroll
        for (int k = 0; k < NSLOTS; ++k) {
            int s = tid + k * NTHREADS;
            float em = ((firstM >> k) & 1u) ? bt0 : nbt0;
            sm[OFF_B0 + s] = em - logS;   // pads get a finite value, harmless
        }
    }
    __syncthreads();
    if (tid < NI) {  // pl0, vf0, plbuf row 1
        int i = tid;
        float plv = sm[OFF_B0 + base_of(i + 1) - 1];
        sm[OFF_PL0 + i] = plv;
        g_plbuf[b][1][i] = plv;
        sm[OFF_VF0 + i] = sm[OFF_B0 + base_of(i)];
    }

    // ---- forward Viterbi: one barrier per step, unrolled x2 by parity ----
#define STEP(T, CUR, ST, PLPREV, PLCUR, VFCUR, LIDX) do {                         \
        __syncthreads();                                                          \
        const float nbt = sm[OFF_NB + (T)];                                       \
        if (wrp < 21) {                                                           \
            const float4 p0 = *(const float4*)&sm[(PLPREV) + 4 * rg];             \
            const float4 p1 = *(const float4*)&sm[(PLPREV) + 32 + 4 * rg];        \
            const float4 p2 = *(const float4*)&sm[(PLPREV) + 64 + 4 * rg];        \
            float a0 = p0.x + tlr[0],  a1 = p0.y + tlr[1];                        \
            a0 = fmaxf(a0, p0.z + tlr[2]);  a1 = fmaxf(a1, p0.w + tlr[3]);        \
            a0 = fmaxf(a0, p1.x + tlr[4]);  a1 = fmaxf(a1, p1.y + tlr[5]);        \
            a0 = fmaxf(a0, p1.z + tlr[6]);  a1 = fmaxf(a1, p1.w + tlr[7]);        \
            a0 = fmaxf(a0, p2.x + tlr[8]);  a1 = fmaxf(a1, p2.y + tlr[9]);        \
            a0 = fmaxf(a0, p2.z + tlr[10]); a1 = fmaxf(a1, p2.w + tlr[11]);       \
            float best = fmaxf(a0, a1);                                           \
            best = fmaxf(best, __shfl_xor_sync(0xffffffffu, best, 1));            \
            best = fmaxf(best, __shfl_xor_sync(0xffffffffu, best, 2));            \
            best = fmaxf(best, __shfl_xor_sync(0xffffffffu, best, 4));            \
            if (rg == 0 && rj < NI)                                               \
                sm[(VFCUR) + rj] = best + sm[OFF_BLP + (T)];                      \
        } else if (plThread) {                                                    \
            float plv = sm[(CUR) + lastm1] + nbt;                                 \
            sm[(PLCUR) + plIdx] = plv;                                            \
            g_plbuf[b][(T) + 1][plIdx] = plv;                                     \
        }                                                                         \
        float x0 = sm[LIDX[0]] + nbt;  float x1 = sm[LIDX[1]] + nbt;              \
        float x2 = sm[LIDX[2]] + nbt;  float x3 = sm[LIDX[3]] + nbt;              \
        float x4 = sm[LIDX[4]] + nbt;  float x5 = sm[LIDX[5]] + nbt;              \
        float x6 = sm[LIDX[6]] + nbt;  float x7 = sm[LIDX[7]] + nbt;              \
        sm[(ST) + tid             ] = x0;  sm[(ST) + tid + 1 * NTHREADS] = x1;    \
        sm[(ST) + tid + 2*NTHREADS] = x2;  sm[(ST) + tid + 3 * NTHREADS] = x3;    \
        sm[(ST) + tid + 4*NTHREADS] = x4;  sm[(ST) + tid + 5 * NTHREADS] = x5;    \
        sm[(ST) + tid + 6*NTHREADS] = x6;  sm[(ST) + tid + 7 * NTHREADS] = x7;    \
    } while (0)

    for (int t = 1; t < TT - 1; t += 2) {
        STEP(t,     OFF_B0, OFF_B1, OFF_PL0, OFF_PL1, OFF_VF1, lidxO);
        STEP(t + 1, OFF_B1, OFF_B0, OFF_PL1, OFF_PL0, OFF_VF0, lidxE);
    }
    STEP(TT - 1, OFF_B0, OFF_B1, OFF_PL0, OFF_PL1, OFF_VF1, lidxO);
    // final delta in buf1 (non-first states); first states in vf1.

    // ---- final argmax over delta(T-1), first-index tiebreak ----
    __syncthreads();
    {
        float bv = NEGINF; int bs = NSTATE - 1;
        #pragma unroll
        for (int k = 0; k < NSLOTS; ++k) {
            if ((validM >> k) & 1u) {
                int s = tid + k * NTHREADS;
                float val;
                if ((firstM >> k) & 1u) {
                    int j = 0;
                    while (j < NI - 1 && base_of(j + 1) <= s) ++j;
                    val = sm[OFF_VF1 + j];
                } else {
                    val = sm[OFF_B1 + s];
                }
                if (val > bv) { bv = val; bs = s; }
            }
        }
        sm[OFF_RV + tid] = bv;
        ((int*)sm)[OFF_RI + tid] = bs;
    }
    __syncthreads();
    if (tid < NTHREADS - 512) {   // fold 512..767 into 0..255
        float v2 = sm[OFF_RV + tid + 512]; int s2 = ((int*)sm)[OFF_RI + tid + 512];
        if (v2 > sm[OFF_RV + tid] ||
            (v2 == sm[OFF_RV + tid] && s2 < ((int*)sm)[OFF_RI + tid])) {
            sm[OFF_RV + tid] = v2; ((int*)sm)[OFF_RI + tid] = s2;
        }
    }
    __syncthreads();
    for (int st = 256; st > 0; st >>= 1) {
        if (tid < st) {
            float v2 = sm[OFF_RV + tid + st]; int s2 = ((int*)sm)[OFF_RI + tid + st];
            if (v2 > sm[OFF_RV + tid] ||
                (v2 == sm[OFF_RV + tid] && s2 < ((int*)sm)[OFF_RI + tid])) {
                sm[OFF_RV + tid] = v2; ((int*)sm)[OFF_RI + tid] = s2;
            }
        }
        __syncthreads();
    }

    // ---- backtrack (thread 0): jump beat-to-beat, hard-bounded ----
    if (tid == 0) {
        const double p0  = (double)0.05f;
        const double thr = log(p0 / (1.0 - p0));   // logit-space threshold

        int s = ((int*)sm)[OFF_RI + 0];
        if (s < 0) s = 0;
        if (s >= NSTATE) s = NSTATE - 1;
        int j = 0;
        while (j < NI - 1 && base_of(j + 1) <= s) ++j;
        int p = s - base_of(j);
        int t = TT - 1;
        for (int iter = 0; iter < TT; ++iter) {
            if (p > t) break;            // path started mid-block: no beat
            int tb = t - p;              // beat time (position 0)
            double x = (double)lg[tb];
            outrow[tb] = (x >= thr) ? 1.0f : 0.0f;
            if (tb == 0) break;
            const float* row = &g_plbuf[b][tb][0];
            float mx = NEGINF; int bi = 0;
            for (int i = 0; i < NI; ++i) {
                float c = row[i] + sm[OFF_TL + i * NI + j];
                if (c > mx) { mx = c; bi = i; }
            }
            j = bi;
            t = tb - 1;
            p = (MINTAU + j) - 1;
        }
    }
}

extern "C" void kernel_launch(void* const* d_in, const int* in_sizes, int n_in,
                              void* d_out, int out_size)
{
    const float* logit = (const float*)d_in[0];
    float* out = (float*)d_out;

    size_t smem = (size_t)SM_FLOATS * sizeof(float);   // 133,776 B
    cudaFuncSetAttribute(dbn_viterbi_kernel,
                         cudaFuncAttributeMaxDynamicSharedMemorySize, (int)smem);
    dbn_viterbi_kernel<<<BB, NTHREADS, smem>>>(logit, out);
}